// round 8
// baseline (speedup 1.0000x reference)
#include <cuda_runtime.h>
#include <cuda_fp16.h>

#define S_LEN 2048
#define NHEAD 16
#define DHEAD 64
#define BM 64
#define BN 64
#define KSTRH 72    // K smem stride in halves: conflict-free LDS.32 B-frags
#define VTSTRH 72   // Vt smem stride in halves (Vt[d][key])
#define BUF_HALVES (BN * KSTRH + DHEAD * VTSTRH)

static __device__ __forceinline__ unsigned packh2(float lo, float hi) {
    __half2 h = __floats2half2_rn(lo, hi);
    return *(unsigned*)&h;
}

static __device__ __forceinline__ void mma_f16(float* d,
                                               unsigned a0, unsigned a1, unsigned a2, unsigned a3,
                                               unsigned b0, unsigned b1) {
    asm volatile("mma.sync.aligned.m16n8k16.row.col.f32.f16.f16.f32 "
                 "{%0,%1,%2,%3}, {%4,%5,%6,%7}, {%8,%9}, {%0,%1,%2,%3};"
                 : "+f"(d[0]), "+f"(d[1]), "+f"(d[2]), "+f"(d[3])
                 : "r"(a0), "r"(a1), "r"(a2), "r"(a3), "r"(b0), "r"(b1));
}

__global__ __launch_bounds__(128, 3)
void attn_tc5_kernel(const float* __restrict__ Q, const float* __restrict__ K,
                     const float* __restrict__ V, float* __restrict__ Out) {
    extern __shared__ __half smh[];   // 2 buffers: [K: BN x KSTRH][Vt: DHEAD x VTSTRH]

    const int qt   = (gridDim.x - 1) - blockIdx.x;   // heavy tiles first
    const int bh   = blockIdx.y;
    const int b    = bh >> 4;
    const int h    = bh & 15;
    const int qrow = qt * BM;

    const float* Kg = K + (size_t)bh * S_LEN * DHEAD;
    const float* Vg = V + (size_t)bh * S_LEN * DHEAD;

    const int tid  = threadIdx.x;
    const int warp = tid >> 5;
    const int lane = tid & 31;
    const int g    = lane >> 2;
    const int t4   = lane & 3;
    const int r0w  = warp << 4;
    const int row0 = qrow + r0w + g;
    const int row1 = row0 + 8;

    // V staging thread mapping
    const int v_rp = tid & 15;     // key-pair base (keys 2rp, 2rp+1)
    const int v_h  = tid >> 4;     // d-block

    // ---- Q A-fragments (fp16, pre-scaled by 1/8) straight from global ----
    unsigned qa[4][4];
    {
        const float* Qg = Q + ((size_t)bh * S_LEN + qrow + r0w) * DHEAD;
        #pragma unroll
        for (int ks = 0; ks < 4; ks++) {
            const float* rp = Qg + g * DHEAD + 16 * ks + 2 * t4;
            float2 xl = *(const float2*)rp;
            float2 xh = *(const float2*)(rp + 8);
            float2 yl = *(const float2*)(rp + 8 * DHEAD);
            float2 yh = *(const float2*)(rp + 8 * DHEAD + 8);
            qa[ks][0] = packh2(0.125f * xl.x, 0.125f * xl.y);
            qa[ks][1] = packh2(0.125f * yl.x, 0.125f * yl.y);
            qa[ks][2] = packh2(0.125f * xh.x, 0.125f * xh.y);
            qa[ks][3] = packh2(0.125f * yh.x, 0.125f * yh.y);
        }
    }

    float o[8][4];
    #pragma unroll
    for (int nt = 0; nt < 8; nt++)
        #pragma unroll
        for (int e = 0; e < 4; e++) o[nt][e] = 0.f;

    float m0 = -1e30f, m1 = -1e30f, l0 = 0.f, l1 = 0.f;

    // ---- Prologue: stage tile 0 into buffer 0 ----
    {
        __half* Kb = smh;
        __half* Vb = smh + BN * KSTRH;
        float4 kr[8];
        #pragma unroll
        for (int it = 0; it < 8; it++) {
            int i = tid + (it << 7);
            kr[it] = *(const float4*)(Kg + (i >> 4) * DHEAD + ((i & 15) << 2));
        }
        #pragma unroll
        for (int it = 0; it < 8; it++) {
            int i  = tid + (it << 7);
            int r  = i >> 4;
            int d4 = (i & 15) << 2;
            __half2* dst = (__half2*)(Kb + r * KSTRH + d4);
            dst[0] = __floats2half2_rn(kr[it].x, kr[it].y);
            dst[1] = __floats2half2_rn(kr[it].z, kr[it].w);
        }
        #pragma unroll
        for (int u = 0; u < 2; u++)
            #pragma unroll
            for (int kh = 0; kh < 2; kh++) {
                int key = 2 * (v_rp + 16 * kh);
                int dv  = 4 * v_h + 32 * u;
                const float* vp = Vg + key * DHEAD + dv;
                float4 v0 = *(const float4*)vp;
                float4 v1 = *(const float4*)(vp + DHEAD);
                *(__half2*)(Vb + (dv + 0) * VTSTRH + key) = __floats2half2_rn(v0.x, v1.x);
                *(__half2*)(Vb + (dv + 1) * VTSTRH + key) = __floats2half2_rn(v0.y, v1.y);
                *(__half2*)(Vb + (dv + 2) * VTSTRH + key) = __floats2half2_rn(v0.z, v1.z);
                *(__half2*)(Vb + (dv + 3) * VTSTRH + key) = __floats2half2_rn(v0.w, v1.w);
            }
    }

    for (int kt = 0; kt <= qt; kt++) {
        const int cur = kt & 1;
        __half* Kc = smh + cur * BUF_HALVES;
        __half* Vc = Kc + BN * KSTRH;
        __half* Kn = smh + (cur ^ 1) * BUF_HALVES;
        __half* Vn = Kn + BN * KSTRH;
        const bool have_next = (kt < qt);

        // ---- Issue K LDGs for next tile (latency hidden by this iteration) ----
        float4 kr[8];
        if (have_next) {
            const float* Kgt = Kg + (size_t)(kt + 1) * BN * DHEAD;
            #pragma unroll
            for (int it = 0; it < 8; it++) {
                int i = tid + (it << 7);
                kr[it] = *(const float4*)(Kgt + (i >> 4) * DHEAD + ((i & 15) << 2));
            }
        }

        __syncthreads();   // tile kt visible; prior reads of the other buffer complete

        // ---- GEMM1: S = (Q*scale) K^T ----
        float s[8][4];
        #pragma unroll
        for (int nt = 0; nt < 8; nt++) {
            s[nt][0] = 0.f; s[nt][1] = 0.f; s[nt][2] = 0.f; s[nt][3] = 0.f;
            const __half* kb = Kc + (g + 8 * nt) * KSTRH + 2 * t4;
            #pragma unroll
            for (int ks = 0; ks < 4; ks++) {
                unsigned b0 = *(const unsigned*)(kb + 16 * ks);
                unsigned b1 = *(const unsigned*)(kb + 16 * ks + 8);
                mma_f16(s[nt], qa[ks][0], qa[ks][1], qa[ks][2], qa[ks][3], b0, b1);
            }
        }

        // ---- Drain K prefetch into next buffer (frees kr registers) ----
        if (have_next) {
            #pragma unroll
            for (int it = 0; it < 8; it++) {
                int i  = tid + (it << 7);
                int r  = i >> 4;
                int d4 = (i & 15) << 2;
                __half2* dst = (__half2*)(Kn + r * KSTRH + d4);
                dst[0] = __floats2half2_rn(kr[it].x, kr[it].y);
                dst[1] = __floats2half2_rn(kr[it].z, kr[it].w);
            }
        }

        // ---- Causal mask (diagonal tile only) ----
        if (kt == qt) {
            const int colb = (kt << 6) + 2 * t4;
            #pragma unroll
            for (int nt = 0; nt < 8; nt++) {
                int c0 = colb + 8 * nt, c1 = c0 + 1;
                if (c0 > row0) s[nt][0] = -10000.0f;
                if (c1 > row0) s[nt][1] = -10000.0f;
                if (c0 > row1) s[nt][2] = -10000.0f;
                if (c1 > row1) s[nt][3] = -10000.0f;
            }
        }

        // ---- Online softmax; P packed to half2 in regs ----
        float mx0 = -1e30f, mx1 = -1e30f;
        #pragma unroll
        for (int nt = 0; nt < 8; nt++) {
            mx0 = fmaxf(mx0, fmaxf(s[nt][0], s[nt][1]));
            mx1 = fmaxf(mx1, fmaxf(s[nt][2], s[nt][3]));
        }
        mx0 = fmaxf(mx0, __shfl_xor_sync(0xffffffffu, mx0, 1));
        mx0 = fmaxf(mx0, __shfl_xor_sync(0xffffffffu, mx0, 2));
        mx1 = fmaxf(mx1, __shfl_xor_sync(0xffffffffu, mx1, 1));
        mx1 = fmaxf(mx1, __shfl_xor_sync(0xffffffffu, mx1, 2));

        float mn0 = fmaxf(m0, mx0), mn1 = fmaxf(m1, mx1);
        float cr0 = __expf(m0 - mn0), cr1 = __expf(m1 - mn1);

        unsigned ph[8][2];
        float sum0 = 0.f, sum1 = 0.f;
        #pragma unroll
        for (int nt = 0; nt < 8; nt++) {
            float p0 = __expf(s[nt][0] - mn0);
            float p1 = __expf(s[nt][1] - mn0);
            float p2 = __expf(s[nt][2] - mn1);
            float p3 = __expf(s[nt][3] - mn1);
            sum0 += p0 + p1; sum1 += p2 + p3;
            ph[nt][0] = packh2(p0, p1);
            ph[nt][1] = packh2(p2, p3);
        }
        sum0 += __shfl_xor_sync(0xffffffffu, sum0, 1);
        sum0 += __shfl_xor_sync(0xffffffffu, sum0, 2);
        sum1 += __shfl_xor_sync(0xffffffffu, sum1, 1);
        sum1 += __shfl_xor_sync(0xffffffffu, sum1, 2);

        l0 = l0 * cr0 + sum0;
        l1 = l1 * cr1 + sum1;
        m0 = mn0; m1 = mn1;

        #pragma unroll
        for (int nt = 0; nt < 8; nt++) {
            o[nt][0] *= cr0; o[nt][1] *= cr0;
            o[nt][2] *= cr1; o[nt][3] *= cr1;
        }

        // ---- Issue V LDGs for next tile (latency hidden by GEMM2) ----
        float4 va[2][2][2];
        if (have_next) {
            const float* Vgt = Vg + (size_t)(kt + 1) * BN * DHEAD;
            #pragma unroll
            for (int u = 0; u < 2; u++)
                #pragma unroll
                for (int kh = 0; kh < 2; kh++) {
                    int key = 2 * (v_rp + 16 * kh);
                    int dv  = 4 * v_h + 32 * u;
                    const float* vp = Vgt + key * DHEAD + dv;
                    va[u][kh][0] = *(const float4*)vp;
                    va[u][kh][1] = *(const float4*)(vp + DHEAD);
                }
        }

        // ---- GEMM2: O += P V ----
        #pragma unroll
        for (int ks = 0; ks < 4; ks++) {
            unsigned a0 = ph[2 * ks][0];
            unsigned a1 = ph[2 * ks][1];
            unsigned a2 = ph[2 * ks + 1][0];
            unsigned a3 = ph[2 * ks + 1][1];
            const __half* vb = Vc + 16 * ks + 2 * t4;
            #pragma unroll
            for (int nt = 0; nt < 8; nt++) {
                const __half* vp = vb + (g + 8 * nt) * VTSTRH;
                unsigned b0 = *(const unsigned*)vp;
                unsigned b1 = *(const unsigned*)(vp + 8);
                mma_f16(o[nt], a0, a1, a2, a3, b0, b1);
            }
        }

        // ---- Drain V prefetch into next buffer ----
        if (have_next) {
            #pragma unroll
            for (int u = 0; u < 2; u++)
                #pragma unroll
                for (int kh = 0; kh < 2; kh++) {
                    int key = 2 * (v_rp + 16 * kh);
                    int dv  = 4 * v_h + 32 * u;
                    float4 v0 = va[u][kh][0], v1 = va[u][kh][1];
                    *(__half2*)(Vn + (dv + 0) * VTSTRH + key) = __floats2half2_rn(v0.x, v1.x);
                    *(__half2*)(Vn + (dv + 1) * VTSTRH + key) = __floats2half2_rn(v0.y, v1.y);
                    *(__half2*)(Vn + (dv + 2) * VTSTRH + key) = __floats2half2_rn(v0.z, v1.z);
                    *(__half2*)(Vn + (dv + 3) * VTSTRH + key) = __floats2half2_rn(v0.w, v1.w);
                }
        }
    }

    // ---- Epilogue: normalize, write Out[b][s][h*64 + d] ----
    const float inv0 = 1.f / l0;
    const float inv1 = 1.f / l1;
    float* Op0 = Out + ((size_t)b * S_LEN + row0) * (NHEAD * DHEAD) + h * DHEAD;
    float* Op1 = Out + ((size_t)b * S_LEN + row1) * (NHEAD * DHEAD) + h * DHEAD;
    #pragma unroll
    for (int nt = 0; nt < 8; nt++) {
        int col = 8 * nt + 2 * t4;
        *(float2*)(Op0 + col) = make_float2(o[nt][0] * inv0, o[nt][1] * inv0);
        *(float2*)(Op1 + col) = make_float2(o[nt][2] * inv1, o[nt][3] * inv1);
    }
}

extern "C" void kernel_launch(void* const* d_in, const int* in_sizes, int n_in,
                              void* d_out, int out_size) {
    (void)in_sizes; (void)n_in; (void)out_size;
    const float* q = (const float*)d_in[0];
    const float* k = (const float*)d_in[1];
    const float* v = (const float*)d_in[2];
    float* out = (float*)d_out;

    const int smem_bytes = 2 * BUF_HALVES * (int)sizeof(__half);   // 36864 B
    cudaFuncSetAttribute(attn_tc5_kernel,
                         cudaFuncAttributeMaxDynamicSharedMemorySize, smem_bytes);

    dim3 grid(S_LEN / BM, 4 * NHEAD);   // (32, 64)
    attn_tc5_kernel<<<grid, 128, smem_bytes>>>(q, k, v, out);
}

// round 10
// speedup vs baseline: 1.8001x; 1.8001x over previous
#include <cuda_runtime.h>
#include <cuda_fp16.h>

#define S_LEN 2048
#define NHEAD 16
#define DHEAD 64
#define BM 64
#define BN 64
#define KSTRH 72    // K smem stride (halves): conflict-free LDS.32 B-frags
#define VTSTRH 72   // Vt smem stride (halves)
#define BUF_HALVES (BN * KSTRH + DHEAD * VTSTRH)

// fp16 scratch (16 MB each) — __device__ globals, no allocation
__device__ __half g_Kh[(size_t)4 * NHEAD * S_LEN * DHEAD];
__device__ __half g_Vt[(size_t)4 * NHEAD * DHEAD * S_LEN];

static __device__ __forceinline__ unsigned packh2(float lo, float hi) {
    __half2 h = __floats2half2_rn(lo, hi);
    return *(unsigned*)&h;
}

static __device__ __forceinline__ void mma_f16(float* d,
                                               unsigned a0, unsigned a1, unsigned a2, unsigned a3,
                                               unsigned b0, unsigned b1) {
    asm volatile("mma.sync.aligned.m16n8k16.row.col.f32.f16.f16.f32 "
                 "{%0,%1,%2,%3}, {%4,%5,%6,%7}, {%8,%9}, {%0,%1,%2,%3};"
                 : "+f"(d[0]), "+f"(d[1]), "+f"(d[2]), "+f"(d[3])
                 : "r"(a0), "r"(a1), "r"(a2), "r"(a3), "r"(b0), "r"(b1));
}

#define CP_ASYNC16(dst_u32, src_ptr) \
    asm volatile("cp.async.cg.shared.global [%0], [%1], 16;" :: "r"(dst_u32), "l"(src_ptr))
#define CP_COMMIT() asm volatile("cp.async.commit_group;" ::: "memory")
#define CP_WAIT0()  asm volatile("cp.async.wait_group 0;" ::: "memory")

// ---- Pre-pass: K -> fp16 (same layout), V -> fp16 transposed [bh][d][key] ----
__global__ __launch_bounds__(128)
void prep_kernel(const float* __restrict__ K, const float* __restrict__ V) {
    const int kt  = blockIdx.x;
    const int bh  = blockIdx.y;
    const int tid = threadIdx.x;

    const float* Kg = K + ((size_t)bh * S_LEN + (size_t)kt * 64) * DHEAD;
    const float* Vg = V + ((size_t)bh * S_LEN + (size_t)kt * 64) * DHEAD;
    __half* Kh = g_Kh + ((size_t)bh * S_LEN + (size_t)kt * 64) * DHEAD;

    // FIX (R8 bug): 64x64 fp32 tile = 1024 float4 chunks -> 8 iterations, not 4.
    #pragma unroll
    for (int it = 0; it < 8; it++) {
        int i  = tid + (it << 7);
        int r  = i >> 4;
        int d4 = (i & 15) << 2;
        float4 kk = *(const float4*)(Kg + r * DHEAD + d4);
        __half2* dst = (__half2*)(Kh + r * DHEAD + d4);
        dst[0] = __floats2half2_rn(kk.x, kk.y);
        dst[1] = __floats2half2_rn(kk.z, kk.w);
    }

    const int v_rp = tid & 15;
    const int v_h  = tid >> 4;
    #pragma unroll
    for (int u = 0; u < 2; u++)
        #pragma unroll
        for (int kh = 0; kh < 2; kh++) {
            int key = 2 * (v_rp + 16 * kh);
            int dv  = 4 * v_h + 32 * u;
            const float* vp = Vg + key * DHEAD + dv;
            float4 v0 = *(const float4*)vp;
            float4 v1 = *(const float4*)(vp + DHEAD);
            __half* Vt = g_Vt + (size_t)bh * DHEAD * S_LEN + (size_t)kt * 64 + key;
            *(__half2*)(Vt + (size_t)(dv + 0) * S_LEN) = __floats2half2_rn(v0.x, v1.x);
            *(__half2*)(Vt + (size_t)(dv + 1) * S_LEN) = __floats2half2_rn(v0.y, v1.y);
            *(__half2*)(Vt + (size_t)(dv + 2) * S_LEN) = __floats2half2_rn(v0.z, v1.z);
            *(__half2*)(Vt + (size_t)(dv + 3) * S_LEN) = __floats2half2_rn(v0.w, v1.w);
        }
}

__global__ __launch_bounds__(128, 4)
void attn_tc6_kernel(const float* __restrict__ Q, float* __restrict__ Out) {
    extern __shared__ __half smh[];   // 2 stages: [K: BN x KSTRH][Vt: DHEAD x VTSTRH]
    const unsigned smem_b = (unsigned)__cvta_generic_to_shared(smh);

    const int qt   = (gridDim.x - 1) - blockIdx.x;   // heavy tiles first
    const int bh   = blockIdx.y;
    const int b    = bh >> 4;
    const int h    = bh & 15;
    const int qrow = qt * BM;

    const int tid  = threadIdx.x;
    const int warp = tid >> 5;
    const int lane = tid & 31;
    const int g    = lane >> 2;
    const int t4   = lane & 3;
    const int r0w  = warp << 4;
    const int row0 = qrow + r0w + g;
    const int row1 = row0 + 8;

    const char* KhB = (const char*)(g_Kh + (size_t)bh * S_LEN * DHEAD);
    const char* VtB = (const char*)(g_Vt + (size_t)bh * DHEAD * S_LEN);

    // ---- Q A-fragments (fp16, pre-scaled by 1/8) straight from global ----
    unsigned qa[4][4];
    {
        const float* Qg = Q + ((size_t)bh * S_LEN + qrow + r0w) * DHEAD;
        #pragma unroll
        for (int ks = 0; ks < 4; ks++) {
            const float* rp = Qg + g * DHEAD + 16 * ks + 2 * t4;
            float2 xl = *(const float2*)rp;
            float2 xh = *(const float2*)(rp + 8);
            float2 yl = *(const float2*)(rp + 8 * DHEAD);
            float2 yh = *(const float2*)(rp + 8 * DHEAD + 8);
            qa[ks][0] = packh2(0.125f * xl.x, 0.125f * xl.y);
            qa[ks][1] = packh2(0.125f * yl.x, 0.125f * yl.y);
            qa[ks][2] = packh2(0.125f * xh.x, 0.125f * xh.y);
            qa[ks][3] = packh2(0.125f * yh.x, 0.125f * yh.y);
        }
    }

    float o[8][4];
    #pragma unroll
    for (int nt = 0; nt < 8; nt++)
        #pragma unroll
        for (int e = 0; e < 4; e++) o[nt][e] = 0.f;

    float m0 = -1e30f, m1 = -1e30f, l0 = 0.f, l1 = 0.f;

    // ---- async stage of one tile (fp16) into ring slot ----
    auto stage = [&](int kt, int slot) {
        unsigned sb = smem_b + (unsigned)slot * (BUF_HALVES * 2);
        const char* Ksrc = KhB + (size_t)kt * BN * DHEAD * 2;   // contiguous 8 KB tile
        #pragma unroll
        for (int it = 0; it < 4; it++) {
            int c = tid + (it << 7);                 // 0..511 sixteen-byte chunks
            unsigned dst = sb + (unsigned)(c >> 3) * (KSTRH * 2) + (unsigned)(c & 7) * 16;
            CP_ASYNC16(dst, Ksrc + (size_t)c * 16);
        }
        const char* Vsrc = VtB + (size_t)kt * BN * 2;           // 64 rows, S_LEN*2 apart
        unsigned vb = sb + BN * KSTRH * 2;
        #pragma unroll
        for (int it = 0; it < 4; it++) {
            int c = tid + (it << 7);
            int r = c >> 3;
            unsigned dst = vb + (unsigned)r * (VTSTRH * 2) + (unsigned)(c & 7) * 16;
            CP_ASYNC16(dst, Vsrc + (size_t)r * (S_LEN * 2) + (size_t)(c & 7) * 16);
        }
        CP_COMMIT();
    };

    stage(0, 0);   // prologue

    for (int kt = 0; kt <= qt; kt++) {
        const int cur = kt & 1;
        const __half* Kc = smh + cur * BUF_HALVES;
        const __half* Vc = Kc + BN * KSTRH;

        CP_WAIT0();        // tile kt landed
        __syncthreads();   // visible to all; all warps done reading the other slot

        if (kt < qt) stage(kt + 1, cur ^ 1);   // in flight during this compute

        // ---- GEMM1: S = (Q*scale) K^T ----
        float s[8][4];
        #pragma unroll
        for (int nt = 0; nt < 8; nt++) {
            s[nt][0] = 0.f; s[nt][1] = 0.f; s[nt][2] = 0.f; s[nt][3] = 0.f;
            const __half* kb = Kc + (g + 8 * nt) * KSTRH + 2 * t4;
            #pragma unroll
            for (int ks = 0; ks < 4; ks++) {
                unsigned b0 = *(const unsigned*)(kb + 16 * ks);
                unsigned b1 = *(const unsigned*)(kb + 16 * ks + 8);
                mma_f16(s[nt], qa[ks][0], qa[ks][1], qa[ks][2], qa[ks][3], b0, b1);
            }
        }

        // ---- Causal mask (diagonal tile only) ----
        if (kt == qt) {
            const int colb = (kt << 6) + 2 * t4;
            #pragma unroll
            for (int nt = 0; nt < 8; nt++) {
                int c0 = colb + 8 * nt, c1 = c0 + 1;
                if (c0 > row0) s[nt][0] = -10000.0f;
                if (c1 > row0) s[nt][1] = -10000.0f;
                if (c0 > row1) s[nt][2] = -10000.0f;
                if (c1 > row1) s[nt][3] = -10000.0f;
            }
        }

        // ---- Online softmax; P packed to half2 in regs ----
        float mx0 = -1e30f, mx1 = -1e30f;
        #pragma unroll
        for (int nt = 0; nt < 8; nt++) {
            mx0 = fmaxf(mx0, fmaxf(s[nt][0], s[nt][1]));
            mx1 = fmaxf(mx1, fmaxf(s[nt][2], s[nt][3]));
        }
        mx0 = fmaxf(mx0, __shfl_xor_sync(0xffffffffu, mx0, 1));
        mx0 = fmaxf(mx0, __shfl_xor_sync(0xffffffffu, mx0, 2));
        mx1 = fmaxf(mx1, __shfl_xor_sync(0xffffffffu, mx1, 1));
        mx1 = fmaxf(mx1, __shfl_xor_sync(0xffffffffu, mx1, 2));

        float mn0 = fmaxf(m0, mx0), mn1 = fmaxf(m1, mx1);
        float cr0 = __expf(m0 - mn0), cr1 = __expf(m1 - mn1);

        unsigned ph[8][2];
        float sum0 = 0.f, sum1 = 0.f;
        #pragma unroll
        for (int nt = 0; nt < 8; nt++) {
            float p0 = __expf(s[nt][0] - mn0);
            float p1 = __expf(s[nt][1] - mn0);
            float p2 = __expf(s[nt][2] - mn1);
            float p3 = __expf(s[nt][3] - mn1);
            sum0 += p0 + p1; sum1 += p2 + p3;
            ph[nt][0] = packh2(p0, p1);
            ph[nt][1] = packh2(p2, p3);
        }
        sum0 += __shfl_xor_sync(0xffffffffu, sum0, 1);
        sum0 += __shfl_xor_sync(0xffffffffu, sum0, 2);
        sum1 += __shfl_xor_sync(0xffffffffu, sum1, 1);
        sum1 += __shfl_xor_sync(0xffffffffu, sum1, 2);

        l0 = l0 * cr0 + sum0;
        l1 = l1 * cr1 + sum1;
        m0 = mn0; m1 = mn1;

        #pragma unroll
        for (int nt = 0; nt < 8; nt++) {
            o[nt][0] *= cr0; o[nt][1] *= cr0;
            o[nt][2] *= cr1; o[nt][3] *= cr1;
        }

        // ---- GEMM2: O += P V ----
        #pragma unroll
        for (int ks = 0; ks < 4; ks++) {
            unsigned a0 = ph[2 * ks][0];
            unsigned a1 = ph[2 * ks][1];
            unsigned a2 = ph[2 * ks + 1][0];
            unsigned a3 = ph[2 * ks + 1][1];
            const __half* vb = Vc + 16 * ks + 2 * t4;
            #pragma unroll
            for (int nt = 0; nt < 8; nt++) {
                const __half* vp = vb + (g + 8 * nt) * VTSTRH;
                unsigned b0 = *(const unsigned*)vp;
                unsigned b1 = *(const unsigned*)(vp + 8);
                mma_f16(o[nt], a0, a1, a2, a3, b0, b1);
            }
        }
    }

    // ---- Epilogue: normalize, write Out[b][s][h*64 + d] ----
    const float inv0 = 1.f / l0;
    const float inv1 = 1.f / l1;
    float* Op0 = Out + ((size_t)b * S_LEN + row0) * (NHEAD * DHEAD) + h * DHEAD;
    float* Op1 = Out + ((size_t)b * S_LEN + row1) * (NHEAD * DHEAD) + h * DHEAD;
    #pragma unroll
    for (int nt = 0; nt < 8; nt++) {
        int col = 8 * nt + 2 * t4;
        *(float2*)(Op0 + col) = make_float2(o[nt][0] * inv0, o[nt][1] * inv0);
        *(float2*)(Op1 + col) = make_float2(o[nt][2] * inv1, o[nt][3] * inv1);
    }
}

extern "C" void kernel_launch(void* const* d_in, const int* in_sizes, int n_in,
                              void* d_out, int out_size) {
    (void)in_sizes; (void)n_in; (void)out_size;
    const float* q = (const float*)d_in[0];
    const float* k = (const float*)d_in[1];
    const float* v = (const float*)d_in[2];
    float* out = (float*)d_out;

    dim3 pgrid(S_LEN / 64, 4 * NHEAD);
    prep_kernel<<<pgrid, 128>>>(k, v);

    const int smem_bytes = 2 * BUF_HALVES * (int)sizeof(__half);   // 36864 B
    cudaFuncSetAttribute(attn_tc6_kernel,
                         cudaFuncAttributeMaxDynamicSharedMemorySize, smem_bytes);
    dim3 grid(S_LEN / BM, 4 * NHEAD);   // (32, 64)
    attn_tc6_kernel<<<grid, 128, smem_bytes>>>(q, out);
}

// round 11
// speedup vs baseline: 1.9914x; 1.1063x over previous
#include <cuda_runtime.h>
#include <cuda_fp16.h>

#define S_LEN 2048
#define NHEAD 16
#define DHEAD 64
#define BM 64
#define BN 64
#define KSTRH 80    // K smem stride (halves): word bank 8g+2t4 -> conflict-free LDS.64
#define VTSTRH 80   // Vt smem stride (halves): same pattern
#define BUF_HALVES (BN * KSTRH + DHEAD * VTSTRH)

#define QSCALE 0.18033688011112042f   /* 0.125 * log2(e) */
#define MASKVAL (-14426.950408889634f) /* -10000 * log2(e) */

// fp16 scratch — __device__ globals, no allocation
__device__ __half g_Kh[(size_t)4 * NHEAD * S_LEN * DHEAD];
__device__ __half g_Vt[(size_t)4 * NHEAD * DHEAD * S_LEN];  // [bh][d][key], keys permuted per 16-chunk

static __device__ __forceinline__ unsigned packh2(float lo, float hi) {
    __half2 h = __floats2half2_rn(lo, hi);
    return *(unsigned*)&h;
}

static __device__ __forceinline__ void mma_f16(float* d,
                                               unsigned a0, unsigned a1, unsigned a2, unsigned a3,
                                               unsigned b0, unsigned b1) {
    asm volatile("mma.sync.aligned.m16n8k16.row.col.f32.f16.f16.f32 "
                 "{%0,%1,%2,%3}, {%4,%5,%6,%7}, {%8,%9}, {%0,%1,%2,%3};"
                 : "+f"(d[0]), "+f"(d[1]), "+f"(d[2]), "+f"(d[3])
                 : "r"(a0), "r"(a1), "r"(a2), "r"(a3), "r"(b0), "r"(b1));
}

#define CP_ASYNC16(dst_u32, src_ptr) \
    asm volatile("cp.async.cg.shared.global [%0], [%1], 16;" :: "r"(dst_u32), "l"(src_ptr))
#define CP_COMMIT() asm volatile("cp.async.commit_group;" ::: "memory")
#define CP_WAIT0()  asm volatile("cp.async.wait_group 0;" ::: "memory")

// ---- Pre-pass: K -> fp16 (natural layout), V -> fp16 transposed+key-permuted ----
__global__ __launch_bounds__(128)
void prep_kernel(const float* __restrict__ K, const float* __restrict__ V) {
    const int kt  = blockIdx.x;
    const int bh  = blockIdx.y;
    const int tid = threadIdx.x;

    const float* Kg = K + ((size_t)bh * S_LEN + (size_t)kt * 64) * DHEAD;
    const float* Vg = V + ((size_t)bh * S_LEN + (size_t)kt * 64) * DHEAD;
    __half* Kh = g_Kh + ((size_t)bh * S_LEN + (size_t)kt * 64) * DHEAD;

    #pragma unroll
    for (int it = 0; it < 8; it++) {
        int i  = tid + (it << 7);
        int r  = i >> 4;
        int d4 = (i & 15) << 2;
        float4 kk = *(const float4*)(Kg + r * DHEAD + d4);
        __half2* dst = (__half2*)(Kh + r * DHEAD + d4);
        dst[0] = __floats2half2_rn(kk.x, kk.y);
        dst[1] = __floats2half2_rn(kk.z, kk.w);
    }

    // V transpose with within-16 key permutation: pos 4j+r <- key 2j+r ; pos 4j+2+r <- key 8+2j+r
    const int v_rp = tid & 15;
    const int v_h  = tid >> 4;
    #pragma unroll
    for (int u = 0; u < 2; u++)
        #pragma unroll
        for (int kh = 0; kh < 2; kh++) {
            int key = 2 * (v_rp + 16 * kh);           // even key in tile, pair (key, key+1)
            int w   = key & 15;                       // within-16 index (even)
            int pos = (key & ~15) + 4 * ((w & 7) >> 1) + ((w < 8) ? 0 : 2);
            int dv  = 4 * v_h + 32 * u;
            const float* vp = Vg + key * DHEAD + dv;
            float4 v0 = *(const float4*)vp;
            float4 v1 = *(const float4*)(vp + DHEAD);
            __half* Vt = g_Vt + (size_t)bh * DHEAD * S_LEN + (size_t)kt * 64 + pos;
            *(__half2*)(Vt + (size_t)(dv + 0) * S_LEN) = __floats2half2_rn(v0.x, v1.x);
            *(__half2*)(Vt + (size_t)(dv + 1) * S_LEN) = __floats2half2_rn(v0.y, v1.y);
            *(__half2*)(Vt + (size_t)(dv + 2) * S_LEN) = __floats2half2_rn(v0.z, v1.z);
            *(__half2*)(Vt + (size_t)(dv + 3) * S_LEN) = __floats2half2_rn(v0.w, v1.w);
        }
}

__global__ __launch_bounds__(128, 4)
void attn_tc7_kernel(const float* __restrict__ Q, float* __restrict__ Out) {
    extern __shared__ __half smh[];   // 2 stages: [K: BN x KSTRH][Vt: DHEAD x VTSTRH]
    const unsigned smem_b = (unsigned)__cvta_generic_to_shared(smh);

    const int qt   = (gridDim.x - 1) - blockIdx.x;   // heavy tiles first
    const int bh   = blockIdx.y;
    const int b    = bh >> 4;
    const int h    = bh & 15;
    const int qrow = qt * BM;

    const int tid  = threadIdx.x;
    const int warp = tid >> 5;
    const int lane = tid & 31;
    const int g    = lane >> 2;
    const int t4   = lane & 3;
    const int r0w  = warp << 4;
    const int row0 = qrow + r0w + g;
    const int row1 = row0 + 8;

    const char* KhB = (const char*)(g_Kh + (size_t)bh * S_LEN * DHEAD);
    const char* VtB = (const char*)(g_Vt + (size_t)bh * DHEAD * S_LEN);

    // ---- Q A-fragments: one float4 per row per ks. k-map: k=2t4 <-> d=16ks+4t4 (+1,+2,+3) ----
    unsigned qa[4][4];
    {
        const float* Qg = Q + ((size_t)bh * S_LEN + qrow + r0w) * DHEAD;
        #pragma unroll
        for (int ks = 0; ks < 4; ks++) {
            const float* rp = Qg + g * DHEAD + 16 * ks + 4 * t4;
            float4 x = *(const float4*)rp;               // row g
            float4 y = *(const float4*)(rp + 8 * DHEAD); // row g+8
            qa[ks][0] = packh2(QSCALE * x.x, QSCALE * x.y);
            qa[ks][1] = packh2(QSCALE * y.x, QSCALE * y.y);
            qa[ks][2] = packh2(QSCALE * x.z, QSCALE * x.w);
            qa[ks][3] = packh2(QSCALE * y.z, QSCALE * y.w);
        }
    }

    float o[8][4];
    #pragma unroll
    for (int nt = 0; nt < 8; nt++)
        #pragma unroll
        for (int e = 0; e < 4; e++) o[nt][e] = 0.f;

    float m0 = -1e30f, m1 = -1e30f, l0 = 0.f, l1 = 0.f;

    // ---- async stage of one fp16 tile into ring slot ----
    auto stage = [&](int kt, int slot) {
        unsigned sb = smem_b + (unsigned)slot * (BUF_HALVES * 2);
        const char* Ksrc = KhB + (size_t)kt * BN * DHEAD * 2;   // contiguous 8 KB
        #pragma unroll
        for (int it = 0; it < 4; it++) {
            int c = tid + (it << 7);                 // 512 x 16B chunks
            unsigned dst = sb + (unsigned)(c >> 3) * (KSTRH * 2) + (unsigned)(c & 7) * 16;
            CP_ASYNC16(dst, Ksrc + (size_t)c * 16);
        }
        const char* Vsrc = VtB + (size_t)kt * BN * 2;           // 64 rows, S_LEN*2 B apart
        unsigned vb = sb + BN * KSTRH * 2;
        #pragma unroll
        for (int it = 0; it < 4; it++) {
            int c = tid + (it << 7);
            int r = c >> 3;
            unsigned dst = vb + (unsigned)r * (VTSTRH * 2) + (unsigned)(c & 7) * 16;
            CP_ASYNC16(dst, Vsrc + (size_t)r * (S_LEN * 2) + (size_t)(c & 7) * 16);
        }
        CP_COMMIT();
    };

    stage(0, 0);

    for (int kt = 0; kt <= qt; kt++) {
        const int cur = kt & 1;
        const __half* Kc = smh + cur * BUF_HALVES;
        const __half* Vc = Kc + BN * KSTRH;

        CP_WAIT0();
        __syncthreads();

        if (kt < qt) stage(kt + 1, cur ^ 1);

        // ---- GEMM1: one LDS.64 B-frag per MMA ----
        float s[8][4];
        #pragma unroll
        for (int nt = 0; nt < 8; nt++) {
            s[nt][0] = 0.f; s[nt][1] = 0.f; s[nt][2] = 0.f; s[nt][3] = 0.f;
            const __half* kb = Kc + (g + 8 * nt) * KSTRH + 4 * t4;
            #pragma unroll
            for (int ks = 0; ks < 4; ks++) {
                uint2 bb = *(const uint2*)(kb + 16 * ks);   // d=16ks+4t4 .. +3
                mma_f16(s[nt], qa[ks][0], qa[ks][1], qa[ks][2], qa[ks][3], bb.x, bb.y);
            }
        }

        // ---- Causal mask (diagonal tile only), log2 domain ----
        if (kt == qt) {
            const int colb = (kt << 6) + 2 * t4;
            #pragma unroll
            for (int nt = 0; nt < 8; nt++) {
                int c0 = colb + 8 * nt, c1 = c0 + 1;
                if (c0 > row0) s[nt][0] = MASKVAL;
                if (c1 > row0) s[nt][1] = MASKVAL;
                if (c0 > row1) s[nt][2] = MASKVAL;
                if (c1 > row1) s[nt][3] = MASKVAL;
            }
        }

        // ---- Online softmax in log2 domain; P packed to half2 in regs ----
        float mx0 = -1e30f, mx1 = -1e30f;
        #pragma unroll
        for (int nt = 0; nt < 8; nt++) {
            mx0 = fmaxf(mx0, fmaxf(s[nt][0], s[nt][1]));
            mx1 = fmaxf(mx1, fmaxf(s[nt][2], s[nt][3]));
        }
        mx0 = fmaxf(mx0, __shfl_xor_sync(0xffffffffu, mx0, 1));
        mx0 = fmaxf(mx0, __shfl_xor_sync(0xffffffffu, mx0, 2));
        mx1 = fmaxf(mx1, __shfl_xor_sync(0xffffffffu, mx1, 1));
        mx1 = fmaxf(mx1, __shfl_xor_sync(0xffffffffu, mx1, 2));

        float mn0 = fmaxf(m0, mx0), mn1 = fmaxf(m1, mx1);
        float cr0 = exp2f(m0 - mn0), cr1 = exp2f(m1 - mn1);

        unsigned ph[8][2];
        float sum0 = 0.f, sum1 = 0.f;
        #pragma unroll
        for (int nt = 0; nt < 8; nt++) {
            float p0 = exp2f(s[nt][0] - mn0);
            float p1 = exp2f(s[nt][1] - mn0);
            float p2 = exp2f(s[nt][2] - mn1);
            float p3 = exp2f(s[nt][3] - mn1);
            sum0 += p0 + p1; sum1 += p2 + p3;
            ph[nt][0] = packh2(p0, p1);
            ph[nt][1] = packh2(p2, p3);
        }
        sum0 += __shfl_xor_sync(0xffffffffu, sum0, 1);
        sum0 += __shfl_xor_sync(0xffffffffu, sum0, 2);
        sum1 += __shfl_xor_sync(0xffffffffu, sum1, 1);
        sum1 += __shfl_xor_sync(0xffffffffu, sum1, 2);

        l0 = l0 * cr0 + sum0;
        l1 = l1 * cr1 + sum1;
        m0 = mn0; m1 = mn1;

        #pragma unroll
        for (int nt = 0; nt < 8; nt++) {
            o[nt][0] *= cr0; o[nt][1] *= cr0;
            o[nt][2] *= cr1; o[nt][3] *= cr1;
        }

        // ---- GEMM2: one LDS.64 B-frag per MMA (key-permuted Vt) ----
        #pragma unroll
        for (int ks = 0; ks < 4; ks++) {
            unsigned a0 = ph[2 * ks][0];
            unsigned a1 = ph[2 * ks][1];
            unsigned a2 = ph[2 * ks + 1][0];
            unsigned a3 = ph[2 * ks + 1][1];
            const __half* vb = Vc + 16 * ks + 4 * t4;
            #pragma unroll
            for (int nt = 0; nt < 8; nt++) {
                uint2 bb = *(const uint2*)(vb + (g + 8 * nt) * VTSTRH);
                mma_f16(o[nt], a0, a1, a2, a3, bb.x, bb.y);
            }
        }
    }

    // ---- Epilogue ----
    const float inv0 = 1.f / l0;
    const float inv1 = 1.f / l1;
    float* Op0 = Out + ((size_t)b * S_LEN + row0) * (NHEAD * DHEAD) + h * DHEAD;
    float* Op1 = Out + ((size_t)b * S_LEN + row1) * (NHEAD * DHEAD) + h * DHEAD;
    #pragma unroll
    for (int nt = 0; nt < 8; nt++) {
        int col = 8 * nt + 2 * t4;
        *(float2*)(Op0 + col) = make_float2(o[nt][0] * inv0, o[nt][1] * inv0);
        *(float2*)(Op1 + col) = make_float2(o[nt][2] * inv1, o[nt][3] * inv1);
    }
}

extern "C" void kernel_launch(void* const* d_in, const int* in_sizes, int n_in,
                              void* d_out, int out_size) {
    (void)in_sizes; (void)n_in; (void)out_size;
    const float* q = (const float*)d_in[0];
    const float* k = (const float*)d_in[1];
    const float* v = (const float*)d_in[2];
    float* out = (float*)d_out;

    dim3 pgrid(S_LEN / 64, 4 * NHEAD);
    prep_kernel<<<pgrid, 128>>>(k, v);

    const int smem_bytes = 2 * BUF_HALVES * (int)sizeof(__half);   // 40960 B
    cudaFuncSetAttribute(attn_tc7_kernel,
                         cudaFuncAttributeMaxDynamicSharedMemorySize, smem_bytes);
    dim3 grid(S_LEN / BM, 4 * NHEAD);   // (32, 64)
    attn_tc7_kernel<<<grid, 128, smem_bytes>>>(q, out);
}

// round 12
// speedup vs baseline: 2.0002x; 1.0044x over previous
#include <cuda_runtime.h>
#include <cuda_fp16.h>

#define S_LEN 2048
#define NHEAD 16
#define DHEAD 64
#define BM 64
#define BN 64
#define KSTRH 80    // K smem stride (halves): conflict-free LDS.64 B-frags
#define VTSTRH 80   // Vt smem stride (halves)
#define BUF_HALVES (BN * KSTRH + DHEAD * VTSTRH)

#define QSCALE 0.18033688011112042f    /* 0.125 * log2(e) */
#define MASKVAL (-14426.950408889634f) /* -10000 * log2(e) */

// fp16 scratch — __device__ globals, no allocation
__device__ __half g_Kh[(size_t)4 * NHEAD * S_LEN * DHEAD];
__device__ __half g_Vt[(size_t)4 * NHEAD * DHEAD * S_LEN];  // [bh][d][key], keys permuted per 16-chunk

static __device__ __forceinline__ unsigned packh2(float lo, float hi) {
    __half2 h = __floats2half2_rn(lo, hi);
    return *(unsigned*)&h;
}

static __device__ __forceinline__ float ex2(float x) {
    float y;
    asm("ex2.approx.ftz.f32 %0, %1;" : "=f"(y) : "f"(x));
    return y;
}

static __device__ __forceinline__ void mma_f16(float* d,
                                               unsigned a0, unsigned a1, unsigned a2, unsigned a3,
                                               unsigned b0, unsigned b1) {
    asm volatile("mma.sync.aligned.m16n8k16.row.col.f32.f16.f16.f32 "
                 "{%0,%1,%2,%3}, {%4,%5,%6,%7}, {%8,%9}, {%0,%1,%2,%3};"
                 : "+f"(d[0]), "+f"(d[1]), "+f"(d[2]), "+f"(d[3])
                 : "r"(a0), "r"(a1), "r"(a2), "r"(a3), "r"(b0), "r"(b1));
}

#define CP_ASYNC16(dst_u32, src_ptr) \
    asm volatile("cp.async.cg.shared.global [%0], [%1], 16;" :: "r"(dst_u32), "l"(src_ptr))
#define CP_COMMIT() asm volatile("cp.async.commit_group;" ::: "memory")
#define CP_WAIT0()  asm volatile("cp.async.wait_group 0;" ::: "memory")

// ---- Pre-pass: K -> fp16 (natural layout), V -> fp16 transposed+key-permuted ----
__global__ __launch_bounds__(128)
void prep_kernel(const float* __restrict__ K, const float* __restrict__ V) {
    const int kt  = blockIdx.x;
    const int bh  = blockIdx.y;
    const int tid = threadIdx.x;

    const float* Kg = K + ((size_t)bh * S_LEN + (size_t)kt * 64) * DHEAD;
    const float* Vg = V + ((size_t)bh * S_LEN + (size_t)kt * 64) * DHEAD;
    __half* Kh = g_Kh + ((size_t)bh * S_LEN + (size_t)kt * 64) * DHEAD;

    #pragma unroll
    for (int it = 0; it < 8; it++) {
        int i  = tid + (it << 7);
        int r  = i >> 4;
        int d4 = (i & 15) << 2;
        float4 kk = *(const float4*)(Kg + r * DHEAD + d4);
        __half2* dst = (__half2*)(Kh + r * DHEAD + d4);
        dst[0] = __floats2half2_rn(kk.x, kk.y);
        dst[1] = __floats2half2_rn(kk.z, kk.w);
    }

    // V transpose with within-16 key permutation: pos 4j+r <- key 2j+r ; pos 4j+2+r <- key 8+2j+r
    const int v_rp = tid & 15;
    const int v_h  = tid >> 4;
    #pragma unroll
    for (int u = 0; u < 2; u++)
        #pragma unroll
        for (int kh = 0; kh < 2; kh++) {
            int key = 2 * (v_rp + 16 * kh);
            int w   = key & 15;
            int pos = (key & ~15) + 4 * ((w & 7) >> 1) + ((w < 8) ? 0 : 2);
            int dv  = 4 * v_h + 32 * u;
            const float* vp = Vg + key * DHEAD + dv;
            float4 v0 = *(const float4*)vp;
            float4 v1 = *(const float4*)(vp + DHEAD);
            __half* Vt = g_Vt + (size_t)bh * DHEAD * S_LEN + (size_t)kt * 64 + pos;
            *(__half2*)(Vt + (size_t)(dv + 0) * S_LEN) = __floats2half2_rn(v0.x, v1.x);
            *(__half2*)(Vt + (size_t)(dv + 1) * S_LEN) = __floats2half2_rn(v0.y, v1.y);
            *(__half2*)(Vt + (size_t)(dv + 2) * S_LEN) = __floats2half2_rn(v0.z, v1.z);
            *(__half2*)(Vt + (size_t)(dv + 3) * S_LEN) = __floats2half2_rn(v0.w, v1.w);
        }
}

__global__ __launch_bounds__(128, 5)
void attn_tc8_kernel(const float* __restrict__ Q, float* __restrict__ Out) {
    extern __shared__ __half smh[];   // 2 stages: [K: BN x KSTRH][Vt: DHEAD x VTSTRH]
    const unsigned smem_b = (unsigned)__cvta_generic_to_shared(smh);

    const int qt   = (gridDim.x - 1) - blockIdx.x;   // heavy tiles first
    const int bh   = blockIdx.y;
    const int b    = bh >> 4;
    const int h    = bh & 15;
    const int qrow = qt * BM;

    const int tid  = threadIdx.x;
    const int warp = tid >> 5;
    const int lane = tid & 31;
    const int g    = lane >> 2;
    const int t4   = lane & 3;
    const int r0w  = warp << 4;
    const int row0 = qrow + r0w + g;
    const int row1 = row0 + 8;

    const char* KhB = (const char*)(g_Kh + (size_t)bh * S_LEN * DHEAD);
    const char* VtB = (const char*)(g_Vt + (size_t)bh * DHEAD * S_LEN);

    // ---- Q A-fragments: one float4 per row per ks. k-map: k=2t4 <-> d=16ks+4t4 (+1,+2,+3) ----
    unsigned qa[4][4];
    {
        const float* Qg = Q + ((size_t)bh * S_LEN + qrow + r0w) * DHEAD;
        #pragma unroll
        for (int ks = 0; ks < 4; ks++) {
            const float* rp = Qg + g * DHEAD + 16 * ks + 4 * t4;
            float4 x = *(const float4*)rp;
            float4 y = *(const float4*)(rp + 8 * DHEAD);
            qa[ks][0] = packh2(QSCALE * x.x, QSCALE * x.y);
            qa[ks][1] = packh2(QSCALE * y.x, QSCALE * y.y);
            qa[ks][2] = packh2(QSCALE * x.z, QSCALE * x.w);
            qa[ks][3] = packh2(QSCALE * y.z, QSCALE * y.w);
        }
    }

    float o[8][4];
    #pragma unroll
    for (int nt = 0; nt < 8; nt++)
        #pragma unroll
        for (int e = 0; e < 4; e++) o[nt][e] = 0.f;

    float m0 = -1e30f, m1 = -1e30f, l0 = 0.f, l1 = 0.f;

    // ---- async stage of one fp16 tile into ring slot ----
    auto stage = [&](int kt, int slot) {
        unsigned sb = smem_b + (unsigned)slot * (BUF_HALVES * 2);
        const char* Ksrc = KhB + (size_t)kt * BN * DHEAD * 2;
        #pragma unroll
        for (int it = 0; it < 4; it++) {
            int c = tid + (it << 7);
            unsigned dst = sb + (unsigned)(c >> 3) * (KSTRH * 2) + (unsigned)(c & 7) * 16;
            CP_ASYNC16(dst, Ksrc + (size_t)c * 16);
        }
        const char* Vsrc = VtB + (size_t)kt * BN * 2;
        unsigned vb = sb + BN * KSTRH * 2;
        #pragma unroll
        for (int it = 0; it < 4; it++) {
            int c = tid + (it << 7);
            int r = c >> 3;
            unsigned dst = vb + (unsigned)r * (VTSTRH * 2) + (unsigned)(c & 7) * 16;
            CP_ASYNC16(dst, Vsrc + (size_t)r * (S_LEN * 2) + (size_t)(c & 7) * 16);
        }
        CP_COMMIT();
    };

    stage(0, 0);

    for (int kt = 0; kt <= qt; kt++) {
        const int cur = kt & 1;
        const __half* Kc = smh + cur * BUF_HALVES;
        const __half* Vc = Kc + BN * KSTRH;

        CP_WAIT0();
        __syncthreads();

        if (kt < qt) stage(kt + 1, cur ^ 1);

        // ---- GEMM1: one LDS.64 B-frag per MMA ----
        float s[8][4];
        #pragma unroll
        for (int nt = 0; nt < 8; nt++) {
            s[nt][0] = 0.f; s[nt][1] = 0.f; s[nt][2] = 0.f; s[nt][3] = 0.f;
            const __half* kb = Kc + (g + 8 * nt) * KSTRH + 4 * t4;
            #pragma unroll
            for (int ks = 0; ks < 4; ks++) {
                uint2 bb = *(const uint2*)(kb + 16 * ks);
                mma_f16(s[nt], qa[ks][0], qa[ks][1], qa[ks][2], qa[ks][3], bb.x, bb.y);
            }
        }

        // ---- Causal mask (diagonal tile only), log2 domain ----
        if (kt == qt) {
            const int colb = (kt << 6) + 2 * t4;
            #pragma unroll
            for (int nt = 0; nt < 8; nt++) {
                int c0 = colb + 8 * nt, c1 = c0 + 1;
                if (c0 > row0) s[nt][0] = MASKVAL;
                if (c1 > row0) s[nt][1] = MASKVAL;
                if (c0 > row1) s[nt][2] = MASKVAL;
                if (c1 > row1) s[nt][3] = MASKVAL;
            }
        }

        // ---- Online softmax in log2 domain (tree reductions); P packed in regs ----
        float a0r[8], a1r[8];
        #pragma unroll
        for (int nt = 0; nt < 8; nt++) {
            a0r[nt] = fmaxf(s[nt][0], s[nt][1]);
            a1r[nt] = fmaxf(s[nt][2], s[nt][3]);
        }
        #pragma unroll
        for (int st = 4; st >= 1; st >>= 1)
            #pragma unroll
            for (int i = 0; i < st; i++) {
                a0r[i] = fmaxf(a0r[i], a0r[i + st]);
                a1r[i] = fmaxf(a1r[i], a1r[i + st]);
            }
        float mx0 = a0r[0], mx1 = a1r[0];
        mx0 = fmaxf(mx0, __shfl_xor_sync(0xffffffffu, mx0, 1));
        mx0 = fmaxf(mx0, __shfl_xor_sync(0xffffffffu, mx0, 2));
        mx1 = fmaxf(mx1, __shfl_xor_sync(0xffffffffu, mx1, 1));
        mx1 = fmaxf(mx1, __shfl_xor_sync(0xffffffffu, mx1, 2));

        float mn0 = fmaxf(m0, mx0), mn1 = fmaxf(m1, mx1);
        float cr0 = ex2(m0 - mn0), cr1 = ex2(m1 - mn1);

        unsigned ph[8][2];
        #pragma unroll
        for (int nt = 0; nt < 8; nt++) {
            float p0 = ex2(s[nt][0] - mn0);
            float p1 = ex2(s[nt][1] - mn0);
            float p2 = ex2(s[nt][2] - mn1);
            float p3 = ex2(s[nt][3] - mn1);
            a0r[nt] = p0 + p1;
            a1r[nt] = p2 + p3;
            ph[nt][0] = packh2(p0, p1);
            ph[nt][1] = packh2(p2, p3);
        }
        #pragma unroll
        for (int st = 4; st >= 1; st >>= 1)
            #pragma unroll
            for (int i = 0; i < st; i++) {
                a0r[i] += a0r[i + st];
                a1r[i] += a1r[i + st];
            }
        float sum0 = a0r[0], sum1 = a1r[0];
        sum0 += __shfl_xor_sync(0xffffffffu, sum0, 1);
        sum0 += __shfl_xor_sync(0xffffffffu, sum0, 2);
        sum1 += __shfl_xor_sync(0xffffffffu, sum1, 1);
        sum1 += __shfl_xor_sync(0xffffffffu, sum1, 2);

        l0 = l0 * cr0 + sum0;
        l1 = l1 * cr1 + sum1;
        m0 = mn0; m1 = mn1;

        #pragma unroll
        for (int nt = 0; nt < 8; nt++) {
            o[nt][0] *= cr0; o[nt][1] *= cr0;
            o[nt][2] *= cr1; o[nt][3] *= cr1;
        }

        // ---- GEMM2: one LDS.64 B-frag per MMA (key-permuted Vt) ----
        #pragma unroll
        for (int ks = 0; ks < 4; ks++) {
            unsigned pa0 = ph[2 * ks][0];
            unsigned pa1 = ph[2 * ks][1];
            unsigned pa2 = ph[2 * ks + 1][0];
            unsigned pa3 = ph[2 * ks + 1][1];
            const __half* vb = Vc + 16 * ks + 4 * t4;
            #pragma unroll
            for (int nt = 0; nt < 8; nt++) {
                uint2 bb = *(const uint2*)(vb + (g + 8 * nt) * VTSTRH);
                mma_f16(o[nt], pa0, pa1, pa2, pa3, bb.x, bb.y);
            }
        }
    }

    // ---- Epilogue ----
    const float inv0 = 1.f / l0;
    const float inv1 = 1.f / l1;
    float* Op0 = Out + ((size_t)b * S_LEN + row0) * (NHEAD * DHEAD) + h * DHEAD;
    float* Op1 = Out + ((size_t)b * S_LEN + row1) * (NHEAD * DHEAD) + h * DHEAD;
    #pragma unroll
    for (int nt = 0; nt < 8; nt++) {
        int col = 8 * nt + 2 * t4;
        *(float2*)(Op0 + col) = make_float2(o[nt][0] * inv0, o[nt][1] * inv0);
        *(float2*)(Op1 + col) = make_float2(o[nt][2] * inv1, o[nt][3] * inv1);
    }
}

extern "C" void kernel_launch(void* const* d_in, const int* in_sizes, int n_in,
                              void* d_out, int out_size) {
    (void)in_sizes; (void)n_in; (void)out_size;
    const float* q = (const float*)d_in[0];
    const float* k = (const float*)d_in[1];
    const float* v = (const float*)d_in[2];
    float* out = (float*)d_out;

    dim3 pgrid(S_LEN / 64, 4 * NHEAD);
    prep_kernel<<<pgrid, 128>>>(k, v);

    const int smem_bytes = 2 * BUF_HALVES * (int)sizeof(__half);   // 40960 B
    cudaFuncSetAttribute(attn_tc8_kernel,
                         cudaFuncAttributeMaxDynamicSharedMemorySize, smem_bytes);
    dim3 grid(S_LEN / BM, 4 * NHEAD);   // (32, 64)
    attn_tc8_kernel<<<grid, 128, smem_bytes>>>(q, out);
}